// round 10
// baseline (speedup 1.0000x reference)
#include <cuda_runtime.h>
#include <cuda_fp16.h>
#include <cstdint>

#define NROWS  32768      // B*Q*W
#define DIM    256
#define KCODES 1024
#define NQV    8
#define MARGIN 0.125f

// ---- scratch (device globals: allocation-free rule) ----
__device__ float  g_res[NROWS * DIM];          // fp32 residual
__device__ float  g_rnorm[NROWS];              // per-row ||res||^2
__device__ float  g_cnorm[NQV * KCODES];       // per-code ||c||^2
__device__ double g_loss;
__device__ __half g_ah[NROWS * DIM];           // fl16(2*residual)
__device__ __half g_bh[NQV * KCODES * DIM];    // fl16(codebook)

__device__ __forceinline__ uint32_t smem_u32(const void* p) {
    uint32_t a;
    asm("{ .reg .u64 t; cvta.to.shared.u64 t, %1; cvt.u32.u64 %0, t; }" : "=r"(a) : "l"(p));
    return a;
}

// ============================================================
// init: residual = z ; rnorm ; g_ah = fl16(2z) ; loss = 0
// ============================================================
__global__ void init_kernel(const float* __restrict__ z) {
    __shared__ float warpsum[8];
    int tid = threadIdx.x;
    int row = blockIdx.x * 4 + (tid >> 6);
    int d   = (tid & 63) << 2;
    size_t off = (size_t)row * DIM + d;

    float4 v = *(const float4*)&z[off];
    *(float4*)&g_res[off] = v;
    *(__half2*)&g_ah[off]     = __floats2half2_rn(2.f * v.x, 2.f * v.y);
    *(__half2*)&g_ah[off + 2] = __floats2half2_rn(2.f * v.z, 2.f * v.w);

    float ls = v.x * v.x + v.y * v.y + v.z * v.z + v.w * v.w;
    #pragma unroll
    for (int s = 16; s >= 1; s >>= 1) ls += __shfl_xor_sync(0xffffffffu, ls, s);
    if ((tid & 31) == 0) warpsum[tid >> 5] = ls;
    __syncthreads();
    if (tid < 4) g_rnorm[blockIdx.x * 4 + tid] = warpsum[2 * tid] + warpsum[2 * tid + 1];
    if (blockIdx.x == 0 && tid == 0) g_loss = 0.0;
}

// ============================================================
// cbprep: g_bh = fl16(cb) for all stages
// ============================================================
__global__ void cbprep_kernel(const float* __restrict__ cbs) {
    size_t i = (size_t)(blockIdx.x * blockDim.x + threadIdx.x) * 4;
    float4 c = *(const float4*)&cbs[i];
    *(__half2*)&g_bh[i]     = __floats2half2_rn(c.x, c.y);
    *(__half2*)&g_bh[i + 2] = __floats2half2_rn(c.z, c.w);
}

// ============================================================
// cnorm
// ============================================================
__global__ void cnorm_kernel(const float* __restrict__ cbs) {
    int gw   = (blockIdx.x * blockDim.x + threadIdx.x) >> 5;
    int lane = threadIdx.x & 31;
    const float* c = cbs + (size_t)gw * DIM;
    float s = 0.f;
    #pragma unroll
    for (int d = lane; d < DIM; d += 32) { float v = c[d]; s += v * v; }
    #pragma unroll
    for (int sh = 16; sh >= 1; sh >>= 1) s += __shfl_xor_sync(0xffffffffu, s, sh);
    if (lane == 0) g_cnorm[gw] = s;
}

// ============================================================
// fused coarse(HMMA) + refine(exact fp32) + update
//   64 rows/CTA, 512 threads (16 warps = 4 row-grp x 4 code-qtr),
//   3-deep cp.async B pipeline, min folded into MMA epilogue
// ============================================================
#define RC      64
#define APITCH  264
#define ABYTES  (RC * APITCH * 2)         // 33792
#define BPITCH  72
#define BTILE   (128 * BPITCH * 2)        // 18432
#define NBUF    3
#define MOFF    (ABYTES + NBUF * BTILE)   // minpart region (4*64 floats)
#define DOFF    (MOFF + 1024)             // dist region
#define DPITCH  1032
#define DBYTES  (RC * DPITCH * 2)         // 132096
#define SMEM_TOTAL (DOFF + DBYTES)        // 222208
#define NTILES  32                        // 8 nc * 4 kc

__device__ __forceinline__ void ldmatrix_x4(uint32_t& r0, uint32_t& r1, uint32_t& r2, uint32_t& r3, uint32_t addr) {
    asm volatile("ldmatrix.sync.aligned.m8n8.x4.shared.b16 {%0,%1,%2,%3}, [%4];"
                 : "=r"(r0), "=r"(r1), "=r"(r2), "=r"(r3) : "r"(addr));
}
__device__ __forceinline__ void mma16816(float* c, uint32_t a0, uint32_t a1, uint32_t a2, uint32_t a3,
                                         uint32_t b0, uint32_t b1) {
    asm volatile("mma.sync.aligned.m16n8k16.row.col.f32.f16.f16.f32 "
                 "{%0,%1,%2,%3}, {%4,%5,%6,%7}, {%8,%9}, {%0,%1,%2,%3};"
                 : "+f"(c[0]), "+f"(c[1]), "+f"(c[2]), "+f"(c[3])
                 : "r"(a0), "r"(a1), "r"(a2), "r"(a3), "r"(b0), "r"(b1));
}
#define CPASYNC16(s, g) asm volatile("cp.async.cg.shared.global [%0], [%1], 16;" :: "r"(s), "l"(g))

extern "C" __global__ void __launch_bounds__(512, 1)
rvq_stage_kernel(const float* __restrict__ cb,
                 float* __restrict__ out_tok, int stage)
{
    extern __shared__ char sm[];
    const uint32_t smb = smem_u32(sm);
    const int tid  = threadIdx.x;
    const int wid  = tid >> 5;
    const int lane = tid & 31;
    const int rowBase = blockIdx.x * RC;

    const int wr = wid & 3;            // warp row-group (16 rows)
    const int wc = wid >> 2;           // warp code-quarter (32 of 128)

    // ---- A tile: fl16(2*res), 64 rows x 256 halves ----
    {
        const __half* ap = g_ah + (size_t)rowBase * DIM;
        #pragma unroll
        for (int i = 0; i < 4; i++) {
            int idx = tid + i * 512;       // 2048 uint4
            int r   = idx >> 5;
            int c8  = idx & 31;
            *(uint4*)(sm + (r * APITCH + c8 * 8) * 2) = *(const uint4*)(ap + (size_t)r * DIM + c8 * 8);
        }
    }
    __syncthreads();

    const float* __restrict__ cnorm = g_cnorm + (size_t)stage * KCODES;
    const __half* __restrict__ bh0  = g_bh + (size_t)stage * KCODES * DIM;

    const int aRow   = wr * 16 + (lane & 7) + 8 * ((lane >> 3) & 1);
    const int aCol8  = (lane >> 4) * 8;
    const uint32_t aBase = smb + (aRow * APITCH + aCol8) * 2;
    const int bN     = (lane & 7) + 8 * ((lane >> 4) & 1);
    const int bK8    = 8 * ((lane >> 3) & 1);
    const uint32_t bFragBase = (uint32_t)(((wc * 32 + bN) * BPITCH + bK8) * 2);

    const int ldRow = tid >> 3;        // 0..63
    const int ldSeg = tid & 7;

    float acc[4][4];
    #pragma unroll
    for (int nb = 0; nb < 4; nb++)
        #pragma unroll
        for (int q = 0; q < 4; q++) acc[nb][q] = 0.f;

    float minLo = 3.402823466e38f, minHi = 3.402823466e38f;   // running row-mins

    // ---- prefetch tiles 0,1 ----
    #pragma unroll
    for (int pf = 0; pf < 2; pf++) {
        const __half* gb = bh0 + (size_t)0 * DIM + pf * 64;    // nc0, kc=pf
        uint32_t dstb = smb + ABYTES + pf * BTILE;
        #pragma unroll
        for (int i = 0; i < 2; i++) {
            int r = ldRow + i * 64;
            CPASYNC16(dstb + (r * BPITCH + ldSeg * 8) * 2,
                      gb + (size_t)r * DIM + ldSeg * 8);
        }
        asm volatile("cp.async.commit_group;");
    }

    for (int tt = 0; tt < NTILES; tt++) {
        if (tt + 2 < NTILES) {
            int t2 = tt + 2;
            int nc2 = t2 >> 2, kc2 = t2 & 3;
            const __half* gb = bh0 + ((size_t)nc2 * 128) * DIM + kc2 * 64;
            uint32_t dstb = smb + ABYTES + (t2 % NBUF) * BTILE;
            #pragma unroll
            for (int i = 0; i < 2; i++) {
                int r = ldRow + i * 64;
                CPASYNC16(dstb + (r * BPITCH + ldSeg * 8) * 2,
                          gb + (size_t)r * DIM + ldSeg * 8);
            }
            asm volatile("cp.async.commit_group;");
            asm volatile("cp.async.wait_group 2;");
        } else if (tt + 1 < NTILES) {
            asm volatile("cp.async.wait_group 1;");
        } else {
            asm volatile("cp.async.wait_group 0;");
        }
        __syncthreads();

        const int kc = tt & 3;
        const uint32_t aTile = aBase + (kc * 64) * 2;
        const uint32_t bBuf  = smb + ABYTES + (tt % NBUF) * BTILE + bFragBase;

        #pragma unroll
        for (int ks = 0; ks < 4; ks++) {
            uint32_t a0, a1, a2, a3;
            ldmatrix_x4(a0, a1, a2, a3, aTile + ks * 32);
            #pragma unroll
            for (int nbp = 0; nbp < 2; nbp++) {
                uint32_t r0, r1, r2, r3;
                ldmatrix_x4(r0, r1, r2, r3, bBuf + (nbp * 16 * BPITCH + ks * 16) * 2);
                mma16816(acc[2 * nbp],     a0, a1, a2, a3, r0, r1);
                mma16816(acc[2 * nbp + 1], a0, a1, a2, a3, r2, r3);
            }
        }
        __syncthreads();

        if (kc == 3) {   // epilogue: hm -> fp16 smem dist + running min
            const int nc = tt >> 2;
            const int rlo = wr * 16 + (lane >> 2);
            #pragma unroll
            for (int nb = 0; nb < 4; nb++) {
                int code0 = nc * 128 + wc * 32 + nb * 8 + 2 * (lane & 3);
                float cn0 = __ldg(&cnorm[code0]);
                float cn1 = __ldg(&cnorm[code0 + 1]);
                float hL0 = cn0 - acc[nb][0], hL1 = cn1 - acc[nb][1];
                float hH0 = cn0 - acc[nb][2], hH1 = cn1 - acc[nb][3];
                *(__half2*)(sm + DOFF + ((size_t)rlo * DPITCH + code0) * 2) =
                    __floats2half2_rn(hL0, hL1);
                *(__half2*)(sm + DOFF + ((size_t)(rlo + 8) * DPITCH + code0) * 2) =
                    __floats2half2_rn(hH0, hH1);
                minLo = fminf(minLo, fminf(hL0, hL1));
                minHi = fminf(minHi, fminf(hH0, hH1));
                acc[nb][0] = acc[nb][1] = acc[nb][2] = acc[nb][3] = 0.f;
            }
        }
    }

    // combine running mins: across the 4 lanes (lane&3) sharing each row
    #pragma unroll
    for (int s = 1; s <= 2; s <<= 1) {
        minLo = fminf(minLo, __shfl_xor_sync(0xffffffffu, minLo, s));
        minHi = fminf(minHi, __shfl_xor_sync(0xffffffffu, minHi, s));
    }
    if ((lane & 3) == 0) {
        int rlo = wr * 16 + (lane >> 2);
        ((float*)(sm + MOFF))[wc * RC + rlo]     = minLo;
        ((float*)(sm + MOFF))[wc * RC + rlo + 8] = minHi;
    }
    __syncthreads();

    // ======== refine + update: 4 rows per warp ========
    float wloss = 0.f;
    #pragma unroll
    for (int rr = 0; rr < 4; rr++) {
        const int row_l = wid * 4 + rr;
        const int row   = rowBase + row_l;
        const char* drow = sm + DOFF + (size_t)row_l * DPITCH * 2;
        const float* mp = (const float*)(sm + MOFF);

        float4 rA = ((const float4*)(g_res + (size_t)row * DIM))[lane * 2];
        float4 rB = ((const float4*)(g_res + (size_t)row * DIM))[lane * 2 + 1];
        const float rn = g_rnorm[row];
        const float T  = fminf(fminf(mp[row_l], mp[RC + row_l]),
                               fminf(mp[2 * RC + row_l], mp[3 * RC + row_l])) + MARGIN;

        float bd = 3.402823466e38f;
        int   bi = 0x7fffffff;
        #pragma unroll
        for (int i = 0; i < 16; i++) {
            float2 f = __half22float2(*(const __half2*)(drow + (lane + 32 * i) * 4));
            unsigned m0 = __ballot_sync(0xffffffffu, f.x <= T);
            unsigned m1 = __ballot_sync(0xffffffffu, f.y <= T);
            while (m0 | m1) {
                int c;
                if (m0) { int src = __ffs(m0) - 1; m0 &= m0 - 1; c = 2 * (src + 32 * i); }
                else    { int src = __ffs(m1) - 1; m1 &= m1 - 1; c = 2 * (src + 32 * i) + 1; }
                const float4* cp = (const float4*)(cb + (size_t)c * DIM);
                float4 c0 = cp[lane * 2], c1 = cp[lane * 2 + 1];
                float p = 0.f;
                p = fmaf(2.f * rA.x, c0.x, p); p = fmaf(2.f * rA.y, c0.y, p);
                p = fmaf(2.f * rA.z, c0.z, p); p = fmaf(2.f * rA.w, c0.w, p);
                p = fmaf(2.f * rB.x, c1.x, p); p = fmaf(2.f * rB.y, c1.y, p);
                p = fmaf(2.f * rB.z, c1.z, p); p = fmaf(2.f * rB.w, c1.w, p);
                #pragma unroll
                for (int s = 16; s >= 1; s >>= 1) p += __shfl_xor_sync(0xffffffffu, p, s);
                float dd = __fadd_rn(__fadd_rn(rn, -p), __ldg(&cnorm[c]));
                if (dd < bd || (dd == bd && c < bi)) { bd = dd; bi = c; }
            }
        }

        const float4* cw = (const float4*)(cb + (size_t)bi * DIM);
        float4 c0 = cw[lane * 2], c1 = cw[lane * 2 + 1];
        rA.x -= c0.x; rA.y -= c0.y; rA.z -= c0.z; rA.w -= c0.w;
        rB.x -= c1.x; rB.y -= c1.y; rB.z -= c1.z; rB.w -= c1.w;
        ((float4*)(g_res + (size_t)row * DIM))[lane * 2]     = rA;
        ((float4*)(g_res + (size_t)row * DIM))[lane * 2 + 1] = rB;
        size_t aoff = (size_t)row * DIM + lane * 8;
        *(__half2*)&g_ah[aoff]     = __floats2half2_rn(2.f * rA.x, 2.f * rA.y);
        *(__half2*)&g_ah[aoff + 2] = __floats2half2_rn(2.f * rA.z, 2.f * rA.w);
        *(__half2*)&g_ah[aoff + 4] = __floats2half2_rn(2.f * rB.x, 2.f * rB.y);
        *(__half2*)&g_ah[aoff + 6] = __floats2half2_rn(2.f * rB.z, 2.f * rB.w);

        float ls = rA.x * rA.x + rA.y * rA.y + rA.z * rA.z + rA.w * rA.w
                 + rB.x * rB.x + rB.y * rB.y + rB.z * rB.z + rB.w * rB.w;
        #pragma unroll
        for (int s = 16; s >= 1; s >>= 1) ls += __shfl_xor_sync(0xffffffffu, ls, s);
        if (lane == 0) {
            g_rnorm[row] = ls;
            out_tok[(size_t)row * NQV + stage] = (float)bi;
        }
        wloss += ls;
    }
    if (lane == 0) atomicAdd(&g_loss, (double)wloss);
}

// ============================================================
// finalize: out = z + ((z - res) - z) ; closs scalar
// ============================================================
__global__ void finalize_kernel(const float* __restrict__ z, float* __restrict__ out) {
    int i = blockIdx.x * blockDim.x + threadIdx.x;
    float4 zv = ((const float4*)z)[i];
    float4 rv = ((const float4*)g_res)[i];
    float4 qv;
    qv.x = zv.x + ((zv.x - rv.x) - zv.x);
    qv.y = zv.y + ((zv.y - rv.y) - zv.y);
    qv.z = zv.z + ((zv.z - rv.z) - zv.z);
    qv.w = zv.w + ((zv.w - rv.w) - zv.w);
    ((float4*)out)[i] = qv;
    if (i == 0) {
        double closs = 1.25 * g_loss / ((double)NROWS * (double)DIM * (double)NQV);
        out[(size_t)NROWS * DIM + (size_t)NROWS * NQV] = (float)closs;
    }
}

// ============================================================
extern "C" void kernel_launch(void* const* d_in, const int* in_sizes, int n_in,
                              void* d_out, int out_size) {
    const float* z   = (const float*)d_in[0];   // [16,8,256,256] f32
    const float* cbs = (const float*)d_in[1];   // [8,1024,256]   f32
    float* out     = (float*)d_out;
    float* out_tok = out + (size_t)NROWS * DIM;

    cudaFuncSetAttribute(rvq_stage_kernel, cudaFuncAttributeMaxDynamicSharedMemorySize, SMEM_TOTAL);

    init_kernel<<<NROWS / 4, 256>>>(z);
    cbprep_kernel<<<(NQV * KCODES * DIM / 4) / 256, 256>>>(cbs);
    cnorm_kernel<<<(NQV * KCODES * 32) / 256, 256>>>(cbs);

    for (int s = 0; s < NQV; s++) {
        const float* cb = cbs + (size_t)s * KCODES * DIM;
        rvq_stage_kernel<<<NROWS / RC, 512, SMEM_TOTAL>>>(cb, out_tok, s);
    }

    finalize_kernel<<<(NROWS * DIM / 4) / 256, 256>>>(z, out);
}

// round 12
// speedup vs baseline: 1.1463x; 1.1463x over previous
#include <cuda_runtime.h>
#include <cuda_fp16.h>
#include <cstdint>

#define NROWS  32768      // B*Q*W
#define DIM    256
#define KCODES 1024
#define NQV    8
#define MARGIN 0.125f

// ---- scratch (device globals: allocation-free rule) ----
__device__ float  g_res[NROWS * DIM];          // fp32 residual
__device__ float  g_rnorm[NROWS];              // per-row ||res||^2
__device__ float  g_cnorm[NQV * KCODES];       // per-code ||c||^2
__device__ double g_loss;
__device__ __half g_ah[NROWS * DIM];           // fl16(2*residual)
__device__ __half g_bh[NQV * KCODES * DIM];    // fl16(codebook)

__device__ __forceinline__ uint32_t smem_u32(const void* p) {
    uint32_t a;
    asm("{ .reg .u64 t; cvta.to.shared.u64 t, %1; cvt.u32.u64 %0, t; }" : "=r"(a) : "l"(p));
    return a;
}

// ============================================================
// init: residual = z ; rnorm ; g_ah = fl16(2z) ; loss = 0
// ============================================================
__global__ void init_kernel(const float* __restrict__ z) {
    __shared__ float warpsum[8];
    int tid = threadIdx.x;
    int row = blockIdx.x * 4 + (tid >> 6);
    int d   = (tid & 63) << 2;
    size_t off = (size_t)row * DIM + d;

    float4 v = *(const float4*)&z[off];
    *(float4*)&g_res[off] = v;
    *(__half2*)&g_ah[off]     = __floats2half2_rn(2.f * v.x, 2.f * v.y);
    *(__half2*)&g_ah[off + 2] = __floats2half2_rn(2.f * v.z, 2.f * v.w);

    float ls = v.x * v.x + v.y * v.y + v.z * v.z + v.w * v.w;
    #pragma unroll
    for (int s = 16; s >= 1; s >>= 1) ls += __shfl_xor_sync(0xffffffffu, ls, s);
    if ((tid & 31) == 0) warpsum[tid >> 5] = ls;
    __syncthreads();
    if (tid < 4) g_rnorm[blockIdx.x * 4 + tid] = warpsum[2 * tid] + warpsum[2 * tid + 1];
    if (blockIdx.x == 0 && tid == 0) g_loss = 0.0;
}

// ============================================================
// cbprep: g_bh = fl16(cb) for all stages
// ============================================================
__global__ void cbprep_kernel(const float* __restrict__ cbs) {
    size_t i = (size_t)(blockIdx.x * blockDim.x + threadIdx.x) * 4;
    float4 c = *(const float4*)&cbs[i];
    *(__half2*)&g_bh[i]     = __floats2half2_rn(c.x, c.y);
    *(__half2*)&g_bh[i + 2] = __floats2half2_rn(c.z, c.w);
}

// ============================================================
// cnorm
// ============================================================
__global__ void cnorm_kernel(const float* __restrict__ cbs) {
    int gw   = (blockIdx.x * blockDim.x + threadIdx.x) >> 5;
    int lane = threadIdx.x & 31;
    const float* c = cbs + (size_t)gw * DIM;
    float s = 0.f;
    #pragma unroll
    for (int d = lane; d < DIM; d += 32) { float v = c[d]; s += v * v; }
    #pragma unroll
    for (int sh = 16; sh >= 1; sh >>= 1) s += __shfl_xor_sync(0xffffffffu, s, sh);
    if (lane == 0) g_cnorm[gw] = s;
}

// ============================================================
// fused coarse(HMMA) + refine(exact fp32) + update, 64 rows/CTA,
// 256 threads, 3-buffer cp.async ring, ONE barrier per tile
// (order: prefetch-issue -> wait own -> sync publishes -> MMA)
// ============================================================
#define RC      64
#define APITCH  264
#define ABYTES  (RC * APITCH * 2)         // 33792
#define BPITCH  72
#define BTILE   (128 * BPITCH * 2)        // 18432
#define NBUF    3
#define MOFF    (ABYTES + NBUF * BTILE)   // minpart region 2*64 floats
#define DOFF    (MOFF + 512)
#define DPITCH  1032
#define DBYTES  (RC * DPITCH * 2)         // 132096
#define SMEM_TOTAL (DOFF + DBYTES)        // 221696
#define NTILES  32                        // 8 nc * 4 kc

__device__ __forceinline__ void ldmatrix_x4(uint32_t& r0, uint32_t& r1, uint32_t& r2, uint32_t& r3, uint32_t addr) {
    asm volatile("ldmatrix.sync.aligned.m8n8.x4.shared.b16 {%0,%1,%2,%3}, [%4];"
                 : "=r"(r0), "=r"(r1), "=r"(r2), "=r"(r3) : "r"(addr));
}
__device__ __forceinline__ void mma16816(float* c, uint32_t a0, uint32_t a1, uint32_t a2, uint32_t a3,
                                         uint32_t b0, uint32_t b1) {
    asm volatile("mma.sync.aligned.m16n8k16.row.col.f32.f16.f16.f32 "
                 "{%0,%1,%2,%3}, {%4,%5,%6,%7}, {%8,%9}, {%0,%1,%2,%3};"
                 : "+f"(c[0]), "+f"(c[1]), "+f"(c[2]), "+f"(c[3])
                 : "r"(a0), "r"(a1), "r"(a2), "r"(a3), "r"(b0), "r"(b1));
}
#define CPASYNC16(s, g) asm volatile("cp.async.cg.shared.global [%0], [%1], 16;" :: "r"(s), "l"(g))

extern "C" __global__ void __launch_bounds__(256, 1)
rvq_stage_kernel(const float* __restrict__ cb,
                 float* __restrict__ out_tok, int stage)
{
    extern __shared__ char sm[];
    const uint32_t smb = smem_u32(sm);
    const int tid  = threadIdx.x;
    const int wid  = tid >> 5;
    const int lane = tid & 31;
    const int rowBase = blockIdx.x * RC;

    const int wr = wid & 3;            // warp row-group (16 rows)
    const int wc = wid >> 2;           // warp code-half (64 of 128)

    const float* __restrict__ cnorm = g_cnorm + (size_t)stage * KCODES;
    const __half* __restrict__ bh0  = g_bh + (size_t)stage * KCODES * DIM;

    const int ldRow = tid >> 3;        // 0..31
    const int ldSeg = tid & 7;

    // ---- prefetch B tile 0 into buf 0 ----
    {
        #pragma unroll
        for (int i = 0; i < 4; i++) {
            int r = ldRow + i * 32;
            CPASYNC16(smb + ABYTES + (r * BPITCH + ldSeg * 8) * 2,
                      bh0 + (size_t)r * DIM + ldSeg * 8);
        }
        asm volatile("cp.async.commit_group;");
    }

    // ---- A tile: fl16(2*res), 64 rows x 256 halves ----
    {
        const __half* ap = g_ah + (size_t)rowBase * DIM;
        #pragma unroll
        for (int i = 0; i < 8; i++) {
            int idx = tid + i * 256;
            int r   = idx >> 5;
            int c8  = idx & 31;
            *(uint4*)(sm + (r * APITCH + c8 * 8) * 2) = *(const uint4*)(ap + (size_t)r * DIM + c8 * 8);
        }
    }

    const int aRow   = wr * 16 + (lane & 7) + 8 * ((lane >> 3) & 1);
    const int aCol8  = (lane >> 4) * 8;
    const uint32_t aBase = smb + (aRow * APITCH + aCol8) * 2;
    const int bN     = (lane & 7) + 8 * ((lane >> 4) & 1);
    const int bK8    = 8 * ((lane >> 3) & 1);
    const uint32_t bFragBase = (uint32_t)(((wc * 64 + bN) * BPITCH + bK8) * 2);

    float acc[8][4];
    #pragma unroll
    for (int nb = 0; nb < 8; nb++)
        #pragma unroll
        for (int q = 0; q < 4; q++) acc[nb][q] = 0.f;

    float minLo = 3.402823466e38f, minHi = 3.402823466e38f;

    for (int tt = 0; tt < NTILES; tt++) {
        // 1) issue prefetch for tile tt+1 into buf (tt+1)%3.
        //    Safe: that buffer was last read by MMA tt-2, and the previous
        //    iteration's __syncthreads proved all warps completed it.
        if (tt + 1 < NTILES) {
            int t2 = tt + 1;
            int nc2 = t2 >> 2, kc2 = t2 & 3;
            const __half* gb = bh0 + ((size_t)nc2 * 128) * DIM + kc2 * 64;
            uint32_t dstb = smb + ABYTES + (t2 % NBUF) * BTILE;
            #pragma unroll
            for (int i = 0; i < 4; i++) {
                int r = ldRow + i * 32;
                CPASYNC16(dstb + (r * BPITCH + ldSeg * 8) * 2,
                          gb + (size_t)r * DIM + ldSeg * 8);
            }
            asm volatile("cp.async.commit_group;");
            asm volatile("cp.async.wait_group 1;");   // own copies of tile tt done
        } else {
            asm volatile("cp.async.wait_group 0;");
        }
        // 2) publish everyone's tile-tt copies (each thread has waited);
        //    also licenses the NEXT iteration's prefetch overwrite.
        //    At tt=0 this additionally covers the A-tile stores.
        __syncthreads();

        const int kc = tt & 3;
        const uint32_t aTile = aBase + (kc * 64) * 2;
        const uint32_t bBuf  = smb + ABYTES + (tt % NBUF) * BTILE + bFragBase;

        #pragma unroll
        for (int ks = 0; ks < 4; ks++) {
            uint32_t a0, a1, a2, a3;
            ldmatrix_x4(a0, a1, a2, a3, aTile + ks * 32);
            #pragma unroll
            for (int nbp = 0; nbp < 4; nbp++) {
                uint32_t r0, r1, r2, r3;
                ldmatrix_x4(r0, r1, r2, r3, bBuf + (nbp * 16 * BPITCH + ks * 16) * 2);
                mma16816(acc[2 * nbp],     a0, a1, a2, a3, r0, r1);
                mma16816(acc[2 * nbp + 1], a0, a1, a2, a3, r2, r3);
            }
        }

        if (kc == 3) {   // epilogue (warp-private dist rows; no sync needed)
            const int nc = tt >> 2;
            const int rlo = wr * 16 + (lane >> 2);
            #pragma unroll
            for (int nb = 0; nb < 8; nb++) {
                int code0 = nc * 128 + wc * 64 + nb * 8 + 2 * (lane & 3);
                float cn0 = __ldg(&cnorm[code0]);
                float cn1 = __ldg(&cnorm[code0 + 1]);
                float hL0 = cn0 - acc[nb][0], hL1 = cn1 - acc[nb][1];
                float hH0 = cn0 - acc[nb][2], hH1 = cn1 - acc[nb][3];
                *(__half2*)(sm + DOFF + ((size_t)rlo * DPITCH + code0) * 2) =
                    __floats2half2_rn(hL0, hL1);
                *(__half2*)(sm + DOFF + ((size_t)(rlo + 8) * DPITCH + code0) * 2) =
                    __floats2half2_rn(hH0, hH1);
                minLo = fminf(minLo, fminf(hL0, hL1));
                minHi = fminf(minHi, fminf(hH0, hH1));
                acc[nb][0] = acc[nb][1] = acc[nb][2] = acc[nb][3] = 0.f;
            }
        }
    }

    // combine running mins across the 4 lanes sharing each row
    #pragma unroll
    for (int s = 1; s <= 2; s <<= 1) {
        minLo = fminf(minLo, __shfl_xor_sync(0xffffffffu, minLo, s));
        minHi = fminf(minHi, __shfl_xor_sync(0xffffffffu, minHi, s));
    }
    if ((lane & 3) == 0) {
        int rlo = wr * 16 + (lane >> 2);
        ((float*)(sm + MOFF))[wc * RC + rlo]     = minLo;
        ((float*)(sm + MOFF))[wc * RC + rlo + 8] = minHi;
    }
    __syncthreads();

    // ======== refine + update: 8 rows per warp ========
    const float* mp = (const float*)(sm + MOFF);
    float wloss = 0.f;
    for (int rr = 0; rr < 8; rr++) {
        const int row_l = wid * 8 + rr;
        const int row   = rowBase + row_l;
        const char* drow = sm + DOFF + (size_t)row_l * DPITCH * 2;

        float4 rA = ((const float4*)(g_res + (size_t)row * DIM))[lane * 2];
        float4 rB = ((const float4*)(g_res + (size_t)row * DIM))[lane * 2 + 1];
        const float rn = g_rnorm[row];
        const float T  = fminf(mp[row_l], mp[RC + row_l]) + MARGIN;

        float bd = 3.402823466e38f;
        int   bi = 0x7fffffff;
        #pragma unroll
        for (int i = 0; i < 16; i++) {
            float2 f = __half22float2(*(const __half2*)(drow + (lane + 32 * i) * 4));
            unsigned m0 = __ballot_sync(0xffffffffu, f.x <= T);
            unsigned m1 = __ballot_sync(0xffffffffu, f.y <= T);
            while (m0 | m1) {
                int c;
                if (m0) { int src = __ffs(m0) - 1; m0 &= m0 - 1; c = 2 * (src + 32 * i); }
                else    { int src = __ffs(m1) - 1; m1 &= m1 - 1; c = 2 * (src + 32 * i) + 1; }
                const float4* cp = (const float4*)(cb + (size_t)c * DIM);
                float4 c0 = cp[lane * 2], c1 = cp[lane * 2 + 1];
                float p = 0.f;
                p = fmaf(2.f * rA.x, c0.x, p); p = fmaf(2.f * rA.y, c0.y, p);
                p = fmaf(2.f * rA.z, c0.z, p); p = fmaf(2.f * rA.w, c0.w, p);
                p = fmaf(2.f * rB.x, c1.x, p); p = fmaf(2.f * rB.y, c1.y, p);
                p = fmaf(2.f * rB.z, c1.z, p); p = fmaf(2.f * rB.w, c1.w, p);
                #pragma unroll
                for (int s = 16; s >= 1; s >>= 1) p += __shfl_xor_sync(0xffffffffu, p, s);
                float dd = __fadd_rn(__fadd_rn(rn, -p), __ldg(&cnorm[c]));
                if (dd < bd || (dd == bd && c < bi)) { bd = dd; bi = c; }
            }
        }

        const float4* cw = (const float4*)(cb + (size_t)bi * DIM);
        float4 c0 = cw[lane * 2], c1 = cw[lane * 2 + 1];
        rA.x -= c0.x; rA.y -= c0.y; rA.z -= c0.z; rA.w -= c0.w;
        rB.x -= c1.x; rB.y -= c1.y; rB.z -= c1.z; rB.w -= c1.w;
        ((float4*)(g_res + (size_t)row * DIM))[lane * 2]     = rA;
        ((float4*)(g_res + (size_t)row * DIM))[lane * 2 + 1] = rB;
        size_t aoff = (size_t)row * DIM + lane * 8;
        *(__half2*)&g_ah[aoff]     = __floats2half2_rn(2.f * rA.x, 2.f * rA.y);
        *(__half2*)&g_ah[aoff + 2] = __floats2half2_rn(2.f * rA.z, 2.f * rA.w);
        *(__half2*)&g_ah[aoff + 4] = __floats2half2_rn(2.f * rB.x, 2.f * rB.y);
        *(__half2*)&g_ah[aoff + 6] = __floats2half2_rn(2.f * rB.z, 2.f * rB.w);

        float ls = rA.x * rA.x + rA.y * rA.y + rA.z * rA.z + rA.w * rA.w
                 + rB.x * rB.x + rB.y * rB.y + rB.z * rB.z + rB.w * rB.w;
        #pragma unroll
        for (int s = 16; s >= 1; s >>= 1) ls += __shfl_xor_sync(0xffffffffu, ls, s);
        if (lane == 0) {
            g_rnorm[row] = ls;
            out_tok[(size_t)row * NQV + stage] = (float)bi;
        }
        wloss += ls;
    }
    if (lane == 0) atomicAdd(&g_loss, (double)wloss);
}

// ============================================================
// finalize: out = z + ((z - res) - z) ; closs scalar
// ============================================================
__global__ void finalize_kernel(const float* __restrict__ z, float* __restrict__ out) {
    int i = blockIdx.x * blockDim.x + threadIdx.x;
    float4 zv = ((const float4*)z)[i];
    float4 rv = ((const float4*)g_res)[i];
    float4 qv;
    qv.x = zv.x + ((zv.x - rv.x) - zv.x);
    qv.y = zv.y + ((zv.y - rv.y) - zv.y);
    qv.z = zv.z + ((zv.z - rv.z) - zv.z);
    qv.w = zv.w + ((zv.w - rv.w) - zv.w);
    ((float4*)out)[i] = qv;
    if (i == 0) {
        double closs = 1.25 * g_loss / ((double)NROWS * (double)DIM * (double)NQV);
        out[(size_t)NROWS * DIM + (size_t)NROWS * NQV] = (float)closs;
    }
}

// ============================================================
extern "C" void kernel_launch(void* const* d_in, const int* in_sizes, int n_in,
                              void* d_out, int out_size) {
    const float* z   = (const float*)d_in[0];   // [16,8,256,256] f32
    const float* cbs = (const float*)d_in[1];   // [8,1024,256]   f32
    float* out     = (float*)d_out;
    float* out_tok = out + (size_t)NROWS * DIM;

    cudaFuncSetAttribute(rvq_stage_kernel, cudaFuncAttributeMaxDynamicSharedMemorySize, SMEM_TOTAL);

    init_kernel<<<NROWS / 4, 256>>>(z);
    cbprep_kernel<<<(NQV * KCODES * DIM / 4) / 256, 256>>>(cbs);
    cnorm_kernel<<<(NQV * KCODES * 32) / 256, 256>>>(cbs);

    for (int s = 0; s < NQV; s++) {
        const float* cb = cbs + (size_t)s * KCODES * DIM;
        rvq_stage_kernel<<<NROWS / RC, 256, SMEM_TOTAL>>>(cb, out_tok, s);
    }

    finalize_kernel<<<(NROWS * DIM / 4) / 256, 256>>>(z, out);
}

// round 13
// speedup vs baseline: 1.1659x; 1.0171x over previous
#include <cuda_runtime.h>
#include <cuda_fp16.h>
#include <cstdint>

#define NROWS  32768      // B*Q*W
#define DIM    256
#define KCODES 1024
#define NQV    8
#define MARGIN 0.125f

// ---- scratch (device globals: allocation-free rule) ----
__device__ float  g_res[NROWS * DIM];          // fp32 residual
__device__ float  g_rnorm[NROWS];              // per-row ||res||^2
__device__ float  g_cnorm[NQV * KCODES];       // per-code ||c||^2
__device__ double g_loss;
__device__ __half g_ah[NROWS * DIM];           // fl16(2*residual)
__device__ __half g_bh[NQV * KCODES * DIM];    // fl16(codebook)

__device__ __forceinline__ uint32_t smem_u32(const void* p) {
    uint32_t a;
    asm("{ .reg .u64 t; cvta.to.shared.u64 t, %1; cvt.u32.u64 %0, t; }" : "=r"(a) : "l"(p));
    return a;
}

// ============================================================
// init: residual = z ; rnorm ; g_ah = fl16(2z) ; loss = 0
// ============================================================
__global__ void init_kernel(const float* __restrict__ z) {
    __shared__ float warpsum[8];
    int tid = threadIdx.x;
    int row = blockIdx.x * 4 + (tid >> 6);
    int d   = (tid & 63) << 2;
    size_t off = (size_t)row * DIM + d;

    float4 v = *(const float4*)&z[off];
    *(float4*)&g_res[off] = v;
    *(__half2*)&g_ah[off]     = __floats2half2_rn(2.f * v.x, 2.f * v.y);
    *(__half2*)&g_ah[off + 2] = __floats2half2_rn(2.f * v.z, 2.f * v.w);

    float ls = v.x * v.x + v.y * v.y + v.z * v.z + v.w * v.w;
    #pragma unroll
    for (int s = 16; s >= 1; s >>= 1) ls += __shfl_xor_sync(0xffffffffu, ls, s);
    if ((tid & 31) == 0) warpsum[tid >> 5] = ls;
    __syncthreads();
    if (tid < 4) g_rnorm[blockIdx.x * 4 + tid] = warpsum[2 * tid] + warpsum[2 * tid + 1];
    if (blockIdx.x == 0 && tid == 0) g_loss = 0.0;
}

// ============================================================
// cbprep: g_bh = fl16(cb) for all stages
// ============================================================
__global__ void cbprep_kernel(const float* __restrict__ cbs) {
    size_t i = (size_t)(blockIdx.x * blockDim.x + threadIdx.x) * 4;
    float4 c = *(const float4*)&cbs[i];
    *(__half2*)&g_bh[i]     = __floats2half2_rn(c.x, c.y);
    *(__half2*)&g_bh[i + 2] = __floats2half2_rn(c.z, c.w);
}

// ============================================================
// cnorm
// ============================================================
__global__ void cnorm_kernel(const float* __restrict__ cbs) {
    int gw   = (blockIdx.x * blockDim.x + threadIdx.x) >> 5;
    int lane = threadIdx.x & 31;
    const float* c = cbs + (size_t)gw * DIM;
    float s = 0.f;
    #pragma unroll
    for (int d = lane; d < DIM; d += 32) { float v = c[d]; s += v * v; }
    #pragma unroll
    for (int sh = 16; sh >= 1; sh >>= 1) s += __shfl_xor_sync(0xffffffffu, s, sh);
    if (lane == 0) g_cnorm[gw] = s;
}

// ============================================================
// fused kernel, warp-specialized:
//   warps 0-3 consumers: 16 rows x 128 codes MMA (R8 geometry, acc[16][4])
//   warps 4-7 producers: cp.async B tiles (3-buffer ring)
//   one __syncthreads per tile (R12-proven order)
// ============================================================
#define RC      64
#define APITCH  264
#define ABYTES  (RC * APITCH * 2)         // 33792
#define BPITCH  72
#define BTILE   (128 * BPITCH * 2)        // 18432
#define NBUF    3
#define MOFF    (ABYTES + NBUF * BTILE)   // minpart: 64 floats
#define DOFF    (MOFF + 512)
#define DPITCH  1032
#define DBYTES  (RC * DPITCH * 2)         // 132096
#define SMEM_TOTAL (DOFF + DBYTES)        // 221696
#define NTILES  32                        // 8 nc * 4 kc

__device__ __forceinline__ void ldmatrix_x4(uint32_t& r0, uint32_t& r1, uint32_t& r2, uint32_t& r3, uint32_t addr) {
    asm volatile("ldmatrix.sync.aligned.m8n8.x4.shared.b16 {%0,%1,%2,%3}, [%4];"
                 : "=r"(r0), "=r"(r1), "=r"(r2), "=r"(r3) : "r"(addr));
}
__device__ __forceinline__ void mma16816(float* c, uint32_t a0, uint32_t a1, uint32_t a2, uint32_t a3,
                                         uint32_t b0, uint32_t b1) {
    asm volatile("mma.sync.aligned.m16n8k16.row.col.f32.f16.f16.f32 "
                 "{%0,%1,%2,%3}, {%4,%5,%6,%7}, {%8,%9}, {%0,%1,%2,%3};"
                 : "+f"(c[0]), "+f"(c[1]), "+f"(c[2]), "+f"(c[3])
                 : "r"(a0), "r"(a1), "r"(a2), "r"(a3), "r"(b0), "r"(b1));
}
#define CPASYNC16(s, g) asm volatile("cp.async.cg.shared.global [%0], [%1], 16;" :: "r"(s), "l"(g))

extern "C" __global__ void __launch_bounds__(256, 1)
rvq_stage_kernel(const float* __restrict__ cb,
                 float* __restrict__ out_tok, int stage)
{
    extern __shared__ char sm[];
    const uint32_t smb = smem_u32(sm);
    const int tid  = threadIdx.x;
    const int wid  = tid >> 5;
    const int lane = tid & 31;
    const int rowBase = blockIdx.x * RC;
    const bool isProducer = (wid >= 4);

    const float* __restrict__ cnorm = g_cnorm + (size_t)stage * KCODES;
    const __half* __restrict__ bh0  = g_bh + (size_t)stage * KCODES * DIM;

    // producer thread mapping (128 threads: warps 4-7)
    const int ptid  = tid - 128;            // 0..127 for producers
    const int ldRow = ptid >> 3;            // 0..15
    const int ldSeg = ptid & 7;

    // ---- producers prefetch B tile 0 into buf 0 ----
    if (isProducer) {
        #pragma unroll
        for (int i = 0; i < 8; i++) {
            int r = ldRow + i * 16;
            CPASYNC16(smb + ABYTES + (r * BPITCH + ldSeg * 8) * 2,
                      bh0 + (size_t)r * DIM + ldSeg * 8);
        }
        asm volatile("cp.async.commit_group;");
    }

    // ---- all warps: A tile fl16(2*res), 64 rows x 256 halves ----
    {
        const __half* ap = g_ah + (size_t)rowBase * DIM;
        #pragma unroll
        for (int i = 0; i < 8; i++) {
            int idx = tid + i * 256;
            int r   = idx >> 5;
            int c8  = idx & 31;
            *(uint4*)(sm + (r * APITCH + c8 * 8) * 2) = *(const uint4*)(ap + (size_t)r * DIM + c8 * 8);
        }
    }

    // consumer fragment addressing (R8 geometry: wid 0..3 -> 16 rows, all 128 codes)
    const int aRow   = wid * 16 + (lane & 7) + 8 * ((lane >> 3) & 1);
    const int aCol8  = (lane >> 4) * 8;
    const uint32_t aBase = smb + (aRow * APITCH + aCol8) * 2;
    const int bN     = (lane & 7) + 8 * ((lane >> 4) & 1);
    const int bK8    = 8 * ((lane >> 3) & 1);
    const uint32_t bFragBase = (uint32_t)((bN * BPITCH + bK8) * 2);

    float acc[16][4];
    if (!isProducer) {
        #pragma unroll
        for (int nb = 0; nb < 16; nb++)
            #pragma unroll
            for (int q = 0; q < 4; q++) acc[nb][q] = 0.f;
    }
    float minLo = 3.402823466e38f, minHi = 3.402823466e38f;

    for (int tt = 0; tt < NTILES; tt++) {
        // producers: issue tile tt+1 into buf (tt+1)%3, then retire tile tt
        if (isProducer) {
            if (tt + 1 < NTILES) {
                int t2 = tt + 1;
                int nc2 = t2 >> 2, kc2 = t2 & 3;
                const __half* gb = bh0 + ((size_t)nc2 * 128) * DIM + kc2 * 64;
                uint32_t dstb = smb + ABYTES + (t2 % NBUF) * BTILE;
                #pragma unroll
                for (int i = 0; i < 8; i++) {
                    int r = ldRow + i * 16;
                    CPASYNC16(dstb + (r * BPITCH + ldSeg * 8) * 2,
                              gb + (size_t)r * DIM + ldSeg * 8);
                }
                asm volatile("cp.async.commit_group;");
                asm volatile("cp.async.wait_group 1;");
            } else {
                asm volatile("cp.async.wait_group 0;");
            }
        }
        // publish tile tt to consumers; licenses next overwrite of buf (tt+1)%3
        __syncthreads();

        if (!isProducer) {
            const int kc = tt & 3;
            const uint32_t aTile = aBase + (kc * 64) * 2;
            const uint32_t bBuf  = smb + ABYTES + (tt % NBUF) * BTILE + bFragBase;

            #pragma unroll
            for (int ks = 0; ks < 4; ks++) {
                uint32_t a0, a1, a2, a3;
                ldmatrix_x4(a0, a1, a2, a3, aTile + ks * 32);
                #pragma unroll
                for (int nbp = 0; nbp < 8; nbp++) {
                    uint32_t r0, r1, r2, r3;
                    ldmatrix_x4(r0, r1, r2, r3, bBuf + (nbp * 16 * BPITCH + ks * 16) * 2);
                    mma16816(acc[2 * nbp],     a0, a1, a2, a3, r0, r1);
                    mma16816(acc[2 * nbp + 1], a0, a1, a2, a3, r2, r3);
                }
            }

            if (kc == 3) {   // epilogue: hm -> fp16 smem dist + running min
                const int nc = tt >> 2;
                const int rlo = wid * 16 + (lane >> 2);
                #pragma unroll
                for (int nb = 0; nb < 16; nb++) {
                    int code0 = nc * 128 + nb * 8 + 2 * (lane & 3);
                    float cn0 = __ldg(&cnorm[code0]);
                    float cn1 = __ldg(&cnorm[code0 + 1]);
                    float hL0 = cn0 - acc[nb][0], hL1 = cn1 - acc[nb][1];
                    float hH0 = cn0 - acc[nb][2], hH1 = cn1 - acc[nb][3];
                    *(__half2*)(sm + DOFF + ((size_t)rlo * DPITCH + code0) * 2) =
                        __floats2half2_rn(hL0, hL1);
                    *(__half2*)(sm + DOFF + ((size_t)(rlo + 8) * DPITCH + code0) * 2) =
                        __floats2half2_rn(hH0, hH1);
                    minLo = fminf(minLo, fminf(hL0, hL1));
                    minHi = fminf(minHi, fminf(hH0, hH1));
                    acc[nb][0] = acc[nb][1] = acc[nb][2] = acc[nb][3] = 0.f;
                }
            }
        }
    }

    // consumers publish per-row mins (one value per row, no wc split)
    if (!isProducer) {
        #pragma unroll
        for (int s = 1; s <= 2; s <<= 1) {
            minLo = fminf(minLo, __shfl_xor_sync(0xffffffffu, minLo, s));
            minHi = fminf(minHi, __shfl_xor_sync(0xffffffffu, minHi, s));
        }
        if ((lane & 3) == 0) {
            int rlo = wid * 16 + (lane >> 2);
            ((float*)(sm + MOFF))[rlo]     = minLo;
            ((float*)(sm + MOFF))[rlo + 8] = minHi;
        }
    }
    __syncthreads();

    // ======== refine + update: all 8 warps, 8 rows each ========
    const float* mp = (const float*)(sm + MOFF);
    float wloss = 0.f;
    for (int rr = 0; rr < 8; rr++) {
        const int row_l = wid * 8 + rr;
        const int row   = rowBase + row_l;
        const char* drow = sm + DOFF + (size_t)row_l * DPITCH * 2;

        float4 rA = ((const float4*)(g_res + (size_t)row * DIM))[lane * 2];
        float4 rB = ((const float4*)(g_res + (size_t)row * DIM))[lane * 2 + 1];
        const float rn = g_rnorm[row];
        const float T  = mp[row_l] + MARGIN;

        float bd = 3.402823466e38f;
        int   bi = 0x7fffffff;
        #pragma unroll
        for (int i = 0; i < 16; i++) {
            float2 f = __half22float2(*(const __half2*)(drow + (lane + 32 * i) * 4));
            unsigned m0 = __ballot_sync(0xffffffffu, f.x <= T);
            unsigned m1 = __ballot_sync(0xffffffffu, f.y <= T);
            while (m0 | m1) {
                int c;
                if (m0) { int src = __ffs(m0) - 1; m0 &= m0 - 1; c = 2 * (src + 32 * i); }
                else    { int src = __ffs(m1) - 1; m1 &= m1 - 1; c = 2 * (src + 32 * i) + 1; }
                const float4* cp = (const float4*)(cb + (size_t)c * DIM);
                float4 c0 = cp[lane * 2], c1 = cp[lane * 2 + 1];
                float p = 0.f;
                p = fmaf(2.f * rA.x, c0.x, p); p = fmaf(2.f * rA.y, c0.y, p);
                p = fmaf(2.f * rA.z, c0.z, p); p = fmaf(2.f * rA.w, c0.w, p);
                p = fmaf(2.f * rB.x, c1.x, p); p = fmaf(2.f * rB.y, c1.y, p);
                p = fmaf(2.f * rB.z, c1.z, p); p = fmaf(2.f * rB.w, c1.w, p);
                #pragma unroll
                for (int s = 16; s >= 1; s >>= 1) p += __shfl_xor_sync(0xffffffffu, p, s);
                float dd = __fadd_rn(__fadd_rn(rn, -p), __ldg(&cnorm[c]));
                if (dd < bd || (dd == bd && c < bi)) { bd = dd; bi = c; }
            }
        }

        const float4* cw = (const float4*)(cb + (size_t)bi * DIM);
        float4 c0 = cw[lane * 2], c1 = cw[lane * 2 + 1];
        rA.x -= c0.x; rA.y -= c0.y; rA.z -= c0.z; rA.w -= c0.w;
        rB.x -= c1.x; rB.y -= c1.y; rB.z -= c1.z; rB.w -= c1.w;
        ((float4*)(g_res + (size_t)row * DIM))[lane * 2]     = rA;
        ((float4*)(g_res + (size_t)row * DIM))[lane * 2 + 1] = rB;
        size_t aoff = (size_t)row * DIM + lane * 8;
        *(__half2*)&g_ah[aoff]     = __floats2half2_rn(2.f * rA.x, 2.f * rA.y);
        *(__half2*)&g_ah[aoff + 2] = __floats2half2_rn(2.f * rA.z, 2.f * rA.w);
        *(__half2*)&g_ah[aoff + 4] = __floats2half2_rn(2.f * rB.x, 2.f * rB.y);
        *(__half2*)&g_ah[aoff + 6] = __floats2half2_rn(2.f * rB.z, 2.f * rB.w);

        float ls = rA.x * rA.x + rA.y * rA.y + rA.z * rA.z + rA.w * rA.w
                 + rB.x * rB.x + rB.y * rB.y + rB.z * rB.z + rB.w * rB.w;
        #pragma unroll
        for (int s = 16; s >= 1; s >>= 1) ls += __shfl_xor_sync(0xffffffffu, ls, s);
        if (lane == 0) {
            g_rnorm[row] = ls;
            out_tok[(size_t)row * NQV + stage] = (float)bi;
        }
        wloss += ls;
    }
    if (lane == 0) atomicAdd(&g_loss, (double)wloss);
}

// ============================================================
// finalize: out = z + ((z - res) - z) ; closs scalar
// ============================================================
__global__ void finalize_kernel(const float* __restrict__ z, float* __restrict__ out) {
    int i = blockIdx.x * blockDim.x + threadIdx.x;
    float4 zv = ((const float4*)z)[i];
    float4 rv = ((const float4*)g_res)[i];
    float4 qv;
    qv.x = zv.x + ((zv.x - rv.x) - zv.x);
    qv.y = zv.y + ((zv.y - rv.y) - zv.y);
    qv.z = zv.z + ((zv.z - rv.z) - zv.z);
    qv.w = zv.w + ((zv.w - rv.w) - zv.w);
    ((float4*)out)[i] = qv;
    if (i == 0) {
        double closs = 1.25 * g_loss / ((double)NROWS * (double)DIM * (double)NQV);
        out[(size_t)NROWS * DIM + (size_t)NROWS * NQV] = (float)closs;
    }
}

// ============================================================
extern "C" void kernel_launch(void* const* d_in, const int* in_sizes, int n_in,
                              void* d_out, int out_size) {
    const float* z   = (const float*)d_in[0];   // [16,8,256,256] f32
    const float* cbs = (const float*)d_in[1];   // [8,1024,256]   f32
    float* out     = (float*)d_out;
    float* out_tok = out + (size_t)NROWS * DIM;

    cudaFuncSetAttribute(rvq_stage_kernel, cudaFuncAttributeMaxDynamicSharedMemorySize, SMEM_TOTAL);

    init_kernel<<<NROWS / 4, 256>>>(z);
    cbprep_kernel<<<(NQV * KCODES * DIM / 4) / 256, 256>>>(cbs);
    cnorm_kernel<<<(NQV * KCODES * 32) / 256, 256>>>(cbs);

    for (int s = 0; s < NQV; s++) {
        const float* cb = cbs + (size_t)s * KCODES * DIM;
        rvq_stage_kernel<<<NROWS / RC, 256, SMEM_TOTAL>>>(cb, out_tok, s);
    }

    finalize_kernel<<<(NROWS * DIM / 4) / 256, 256>>>(z, out);
}